// round 6
// baseline (speedup 1.0000x reference)
#include <cuda_runtime.h>
#include <math.h>

#define LSEQ   4096
#define NFFT   4096
#define DMODEL 1024
#define ORDER  64
#define EMB    5

// ---- scratch (static device globals: allowed) ----
__device__ float  g_h3[LSEQ * ORDER];
__device__ float  g_k [DMODEL * LSEQ];
__device__ float  g_decayA[DMODEL * 64];
__device__ float  g_decayB[DMODEL * 64];
__device__ float2 g_tw[1025];    // eighth-wave table of W8192: w[j]=exp(-2*pi*i*j/8192), j in [0,1024]

// =====================================================================
// Kernel 1: implicit-filter MLP. 4 rows per warp, 8 warps -> 32 rows/CTA.
// grid 128. Also fills decay + twiddle tables.
// =====================================================================
#define MLP_BLOCKS 128
__global__ __launch_bounds__(256) void k_filter_mlp(
    const float* __restrict__ z, const float* __restrict__ deltas,
    const float* __restrict__ W1, const float* __restrict__ b1,
    const float* __restrict__ freq, const float* __restrict__ W2,
    const float* __restrict__ b2, const float* __restrict__ W3,
    const float* __restrict__ b3)
{
    __shared__ float sW1[ORDER * EMB], sb1[ORDER], sb2[ORDER], sb3[ORDER], sfreq[ORDER];
    __shared__ float sW2T[ORDER][ORDER + 1];   // transposed: [j][o]
    __shared__ float sW3T[ORDER][ORDER + 1];
    __shared__ float hb1[8][4][ORDER], hb2[8][4][ORDER];

    int tid = threadIdx.x;
    int wid = tid >> 5, lane = tid & 31;

    for (int i = tid; i < ORDER * EMB; i += 256) sW1[i] = W1[i];
    for (int i = tid; i < ORDER * ORDER; i += 256) {
        int o = i >> 6, j = i & 63;
        sW2T[j][o] = W2[i];
        sW3T[j][o] = W3[i];
    }
    if (tid < ORDER) { sb1[tid] = b1[tid]; sb2[tid] = b2[tid]; sb3[tid] = b3[tid]; sfreq[tid] = freq[tid]; }
    __syncthreads();

    int lbase = blockIdx.x * 32 + wid * 4;
    int o0 = lane, o1 = lane + 32;
    float f0 = sfreq[o0], f1 = sfreq[o1];

    // layer 1
    float a0[4], a1[4];
#pragma unroll
    for (int rr = 0; rr < 4; rr++) { a0[rr] = sb1[o0]; a1[rr] = sb1[o1]; }
#pragma unroll
    for (int e = 0; e < EMB; e++) {
        float w0 = sW1[o0 * EMB + e], w1 = sW1[o1 * EMB + e];
#pragma unroll
        for (int rr = 0; rr < 4; rr++) {
            float zv = z[(lbase + rr) * EMB + e];   // broadcast within warp
            a0[rr] += zv * w0;
            a1[rr] += zv * w1;
        }
    }
#pragma unroll
    for (int rr = 0; rr < 4; rr++) {
        hb1[wid][rr][o0] = __sinf(f0 * a0[rr]);
        hb1[wid][rr][o1] = __sinf(f1 * a1[rr]);
    }
    __syncwarp();

    // layer 2
#pragma unroll
    for (int rr = 0; rr < 4; rr++) { a0[rr] = sb2[o0]; a1[rr] = sb2[o1]; }
#pragma unroll 8
    for (int j = 0; j < ORDER; j++) {
        float w0 = sW2T[j][o0], w1 = sW2T[j][o1];
#pragma unroll
        for (int rr = 0; rr < 4; rr++) {
            float hj = hb1[wid][rr][j];
            a0[rr] += hj * w0;
            a1[rr] += hj * w1;
        }
    }
#pragma unroll
    for (int rr = 0; rr < 4; rr++) {
        hb2[wid][rr][o0] = __sinf(f0 * a0[rr]);
        hb2[wid][rr][o1] = __sinf(f1 * a1[rr]);
    }
    __syncwarp();

    // layer 3
#pragma unroll
    for (int rr = 0; rr < 4; rr++) { a0[rr] = sb3[o0]; a1[rr] = sb3[o1]; }
#pragma unroll 8
    for (int j = 0; j < ORDER; j++) {
        float w0 = sW3T[j][o0], w1 = sW3T[j][o1];
#pragma unroll
        for (int rr = 0; rr < 4; rr++) {
            float hj = hb2[wid][rr][j];
            a0[rr] += hj * w0;
            a1[rr] += hj * w1;
        }
    }
#pragma unroll
    for (int rr = 0; rr < 4; rr++) {
        g_h3[(lbase + rr) * ORDER + o0] = __sinf(f0 * a0[rr]);
        g_h3[(lbase + rr) * ORDER + o1] = __sinf(f1 * a1[rr]);
    }

    // decay factorization: decay(d,l) = A[d][l>>6] * B[d][l&63]
    for (int g = blockIdx.x * 256 + tid; g < DMODEL * 64; g += MLP_BLOCKS * 256) {
        int i = g & 63;
        float a = fabsf(deltas[g >> 6]);
        g_decayA[g] = __expf(-a * (64.0f * (float)i) * (1.0f / 4095.0f));
        g_decayB[g] = __expf(-a * (float)i * (1.0f / 4095.0f));
    }
    // eighth-wave twiddle table
    for (int g = blockIdx.x * 256 + tid; g < 1025; g += MLP_BLOCKS * 256) {
        float ang = -2.0f * 3.14159265358979323846f * (float)g * (1.0f / 8192.0f);
        float s, c;
        sincosf(ang, &s, &c);
        g_tw[g] = make_float2(c, s);
    }
}

// =====================================================================
// Kernel 2: k[d][l] = (h3[l][:] . W4[d][:]) * decay(d,l)
// =====================================================================
__global__ __launch_bounds__(256) void k_filter_gemm(const float* __restrict__ W4)
{
    __shared__ float sh[64][65];
    __shared__ float sw[64][65];
    int lt = blockIdx.x, dt = blockIdx.y;
    int tid = threadIdx.x;

    for (int i = tid; i < 64 * 64; i += 256) {
        int row = i >> 6, col = i & 63;
        sh[row][col] = g_h3[(lt * 64 + row) * 64 + col];
        sw[row][col] = W4[(dt * 64 + row) * 64 + col];
    }
    __syncthreads();

    int tx = tid & 15, ty = tid >> 4;
    float acc[4][4];
#pragma unroll
    for (int r = 0; r < 4; r++)
#pragma unroll
        for (int c = 0; c < 4; c++) acc[r][c] = 0.0f;

#pragma unroll 8
    for (int o = 0; o < 64; o++) {
        float a[4], b[4];
#pragma unroll
        for (int r = 0; r < 4; r++) a[r] = sh[tx + 16 * r][o];
#pragma unroll
        for (int c = 0; c < 4; c++) b[c] = sw[ty + 16 * c][o];
#pragma unroll
        for (int r = 0; r < 4; r++)
#pragma unroll
            for (int c = 0; c < 4; c++) acc[r][c] += a[r] * b[c];
    }

#pragma unroll
    for (int c = 0; c < 4; c++) {
        int d = dt * 64 + ty + 16 * c;
        float dA = g_decayA[d * 64 + lt];
#pragma unroll
        for (int r = 0; r < 4; r++) {
            int li = tx + 16 * r;
            g_k[(size_t)d * LSEQ + lt * 64 + li] = acc[r][c] * dA * g_decayB[d * 64 + li];
        }
    }
}

// =====================================================================
// Kernel 3: per-channel convolution via cyclic + negacyclic 4096-pt FFTs.
// y[n] = (cyc[n] + negacyc[n]) / 2 for n < 4096.
// 4096 = 16^3: 3 radix-16 rounds, 256 threads, 1 butterfly/thread.
// FFT<->pointwise seams stay in registers; K spectra live in registers.
// =====================================================================
#define PHI(a) ((a) + ((a) >> 4))
#define ABUF 4352
#define BBUF 4352
#define CBUF 4096
#define TWSZ 1032
#define SMEMF2 (ABUF + BBUF + CBUF + TWSZ)
#define SLOT(r) ((((r) & 3) << 2) | ((r) >> 2))

__device__ __forceinline__ float2 cmul(float2 a, float2 b) {
    return make_float2(a.x * b.x - a.y * b.y, a.x * b.y + a.y * b.x);
}
__device__ __forceinline__ float2 cmulc(float2 a, float cr, float ci) {
    return make_float2(a.x * cr - a.y * ci, a.x * ci + a.y * cr);
}
__device__ __forceinline__ float2 cadd(float2 a, float2 b) { return make_float2(a.x + b.x, a.y + b.y); }
__device__ __forceinline__ float2 csub(float2 a, float2 b) { return make_float2(a.x - b.x, a.y - b.y); }
__device__ __forceinline__ float2 cmulnegi(float2 a) { return make_float2(a.y, -a.x); }

// W8192^e for e in [0,8192): eighth table + reflection + quadrant rotation
__device__ __forceinline__ float2 twget8(const float2* __restrict__ tw, int e) {
    int j = e & 2047;
    float2 c;
    if (j <= 1024) {
        c = tw[j];
    } else {
        float2 t = tw[2048 - j];
        c = make_float2(-t.y, -t.x);
    }
    int k = (e >> 11) & 3;
    if (k == 1)      c = make_float2(c.y, -c.x);
    else if (k == 2) c = make_float2(-c.x, -c.y);
    else if (k == 3) c = make_float2(-c.y, c.x);
    return c;
}

__device__ __forceinline__ void bf4(float2& x0, float2& x1, float2& x2, float2& x3) {
    float2 t0 = cadd(x0, x2), t1 = csub(x0, x2);
    float2 t2 = cadd(x1, x3), t3 = csub(x1, x3);
    float2 it3 = cmulnegi(t3);
    x0 = cadd(t0, t2); x2 = csub(t0, t2);
    x1 = cadd(t1, it3); x3 = csub(t1, it3);
}

#define C16 0.9238795325112867f
#define S16 0.3826834323650898f
#define R2H 0.7071067811865476f

__device__ __forceinline__ void bf16core(float2 a[16]) {
    bf4(a[0], a[4], a[8],  a[12]);
    bf4(a[1], a[5], a[9],  a[13]);
    bf4(a[2], a[6], a[10], a[14]);
    bf4(a[3], a[7], a[11], a[15]);
    a[5]  = cmulc(a[5],  C16, -S16);
    a[9]  = cmulc(a[9],  R2H, -R2H);
    a[13] = cmulc(a[13], S16, -C16);
    a[6]  = cmulc(a[6],  R2H, -R2H);
    a[10] = cmulnegi(a[10]);
    a[14] = cmulc(a[14], -R2H, -R2H);
    a[7]  = cmulc(a[7],  S16, -C16);
    a[11] = cmulc(a[11], -R2H, -R2H);
    a[15] = cmulc(a[15], -C16,  S16);
    bf4(a[0],  a[1],  a[2],  a[3]);
    bf4(a[4],  a[5],  a[6],  a[7]);
    bf4(a[8],  a[9],  a[10], a[11]);
    bf4(a[12], a[13], a[14], a[15]);
}

// Round 1: a[] holds input values at indices tid+256j. Output to dst.
__device__ __forceinline__ void round1_store(float2 a[16], float2* __restrict__ dst,
                                             const float2* __restrict__ tws, int tid)
{
    bf16core(a);
#pragma unroll
    for (int r = 1; r < 16; r++) a[SLOT(r)] = cmul(a[SLOT(r)], twget8(tws, 2 * r * tid));
    __syncthreads();
    int ob = tid << 4;
#pragma unroll
    for (int r = 0; r < 16; r++) { int ad = ob + r; dst[ad + (ad >> 4)] = a[SLOT(r)]; }
    __syncthreads();
}

// Round 2: src -> dst
__device__ __forceinline__ void round2(const float2* __restrict__ src, float2* __restrict__ dst,
                                       const float2* __restrict__ tws, int tid)
{
    float2 a[16];
    int lb = tid + (tid >> 4);
#pragma unroll
    for (int j = 0; j < 16; j++) a[j] = src[lb + 272 * j];
    bf16core(a);
    int sp = tid & ~15;
#pragma unroll
    for (int r = 1; r < 16; r++) a[SLOT(r)] = cmul(a[SLOT(r)], twget8(tws, 2 * r * sp));
    __syncthreads();
    int q = tid & 15, p = tid >> 4;
    int ob = q + (p << 8);
#pragma unroll
    for (int r = 0; r < 16; r++) { int ad = ob + (r << 4); dst[ad + (ad >> 4)] = a[SLOT(r)]; }
    __syncthreads();
}

// Round 3: src -> regs. Twiddle-free (p=0). Value at index tid+256r is a[SLOT(r)].
__device__ __forceinline__ void round3(const float2* __restrict__ src, float2 a[16], int tid)
{
    int lb = tid + (tid >> 4);
#pragma unroll
    for (int j = 0; j < 16; j++) a[j] = src[lb + 272 * j];
    bf16core(a);
}

__global__ __launch_bounds__(256, 2) void k_conv(const float* __restrict__ x,
                                                 const float* __restrict__ bias,
                                                 float* __restrict__ out)
{
    extern __shared__ float2 sm[];
    float2* A   = sm;
    float2* B   = sm + ABUF;
    float2* C   = sm + ABUF + BBUF;          // parking for cyc inverse result
    float2* tws = sm + ABUF + BBUF + CBUF;   // 1025 used

    int tid = threadIdx.x;
    int d = blockIdx.x;

    for (int i = tid; i < 1025; i += 256) tws[i] = g_tw[i];
    __syncthreads();

    const float* kg = g_k + (size_t)d * LSEQ;
    float2 a[16], Kc[16], Kn[16];

    // ---- K cyclic spectrum (registers) ----
#pragma unroll
    for (int j = 0; j < 16; j++) a[j] = make_float2(kg[tid + 256 * j], 0.0f);
    round1_store(a, A, tws, tid);
    round2(A, B, tws, tid);
    round3(B, a, tid);
#pragma unroll
    for (int r = 0; r < 16; r++) Kc[r] = a[SLOT(r)];

    // ---- K negacyclic spectrum: premultiply by psi^j = W8192^j ----
#pragma unroll
    for (int j = 0; j < 16; j++) {
        int i = tid + 256 * j;
        float kv = kg[i];
        float2 w = twget8(tws, i);
        a[j] = make_float2(kv * w.x, kv * w.y);
    }
    round1_store(a, A, tws, tid);
    round2(A, B, tws, tid);
    round3(B, a, tid);
#pragma unroll
    for (int r = 0; r < 16; r++) Kn[r] = a[SLOT(r)];

    float bd = bias[d];
    const float inv2N = 1.0f / 8192.0f;      // 1/(2*4096)

#pragma unroll
    for (int pr = 0; pr < 2; pr++) {
        const float* x0 = x + ((size_t)(2 * pr) * DMODEL + d) * LSEQ;
        const float* x1 = x + ((size_t)(2 * pr + 1) * DMODEL + d) * LSEQ;

        // ---- forward cyclic FFT of packed x0 + i*x1 (gmem -> R1) ----
#pragma unroll
        for (int j = 0; j < 16; j++) {
            int i = tid + 256 * j;
            a[j] = make_float2(x0[i], x1[i]);
        }
        round1_store(a, A, tws, tid);
        round2(A, B, tws, tid);
        round3(B, a, tid);

        // product with Kc + conj, re-permuted to j-order for next R1 (registers only)
        {
            float2 b[16];
#pragma unroll
            for (int j = 0; j < 16; j++) {
                float2 v = cmul(a[SLOT(j)], Kc[j]);
                b[j] = make_float2(v.x, -v.y);
            }
            // ---- inverse cyclic (forward-of-conjugate) ----
            round1_store(b, A, tws, tid);
        }
        round2(A, B, tws, tid);
        round3(B, a, tid);
        // park Fc (barriers of the following round1_store provide ordering)
#pragma unroll
        for (int r = 0; r < 16; r++) C[tid + 256 * r] = a[SLOT(r)];

        // ---- forward negacyclic FFT: premultiply packed input by psi^j ----
#pragma unroll
        for (int j = 0; j < 16; j++) {
            int i = tid + 256 * j;
            float2 v = make_float2(x0[i], x1[i]);
            a[j] = cmul(v, twget8(tws, i));
        }
        round1_store(a, A, tws, tid);
        round2(A, B, tws, tid);
        round3(B, a, tid);

        // product with Kn + conj
        {
            float2 b[16];
#pragma unroll
            for (int j = 0; j < 16; j++) {
                float2 v = cmul(a[SLOT(j)], Kn[j]);
                b[j] = make_float2(v.x, -v.y);
            }
            // ---- inverse negacyclic ----
            round1_store(b, A, tws, tid);
        }
        round2(A, B, tws, tid);
        round3(B, a, tid);

        // ---- combine: y = (cyc + psi^{-n} negacyc)/2, via conj trick ----
        float* o0 = out + ((size_t)(2 * pr) * DMODEL + d) * LSEQ;
        float* o1 = out + ((size_t)(2 * pr + 1) * DMODEL + d) * LSEQ;
#pragma unroll
        for (int r = 0; r < 16; r++) {
            int i = tid + 256 * r;
            float2 Fc = C[i];
            float2 G = cmul(twget8(tws, i), a[SLOT(r)]);
            o0[i] =  (Fc.x + G.x) * inv2N + x0[i] * bd;
            o1[i] = -(Fc.y + G.y) * inv2N + x1[i] * bd;
        }
        __syncthreads();   // C consumed before next iteration's park
    }
}

// =====================================================================
extern "C" void kernel_launch(void* const* d_in, const int* in_sizes, int n_in,
                              void* d_out, int out_size)
{
    (void)n_in; (void)out_size;
    const float* x = (const float*)d_in[0];
    int base = (in_sizes[1] == 1) ? 2 : 1;
    const float* z      = (const float*)d_in[base + 0];
    const float* deltas = (const float*)d_in[base + 2];
    const float* W1     = (const float*)d_in[base + 3];
    const float* b1     = (const float*)d_in[base + 4];
    const float* freq   = (const float*)d_in[base + 5];
    const float* W2     = (const float*)d_in[base + 6];
    const float* b2     = (const float*)d_in[base + 7];
    const float* W3     = (const float*)d_in[base + 8];
    const float* b3     = (const float*)d_in[base + 9];
    const float* W4     = (const float*)d_in[base + 10];
    const float* bias   = (const float*)d_in[base + 11];
    float* out = (float*)d_out;

    k_filter_mlp<<<MLP_BLOCKS, 256>>>(z, deltas, W1, b1, freq, W2, b2, W3, b3);

    dim3 g2(64, 16);
    k_filter_gemm<<<g2, 256>>>(W4);

    const int smem_bytes = SMEMF2 * (int)sizeof(float2);   // 110,656 B -> 2 CTAs/SM
    cudaFuncSetAttribute(k_conv, cudaFuncAttributeMaxDynamicSharedMemorySize, smem_bytes);
    k_conv<<<DMODEL, 256, smem_bytes>>>(x, bias, out);
}

// round 7
// speedup vs baseline: 1.2997x; 1.2997x over previous
#include <cuda_runtime.h>
#include <math.h>

#define LSEQ   4096
#define DMODEL 1024
#define ORDER  64
#define EMB    5

// ---- scratch (static device globals: allowed) ----
__device__ float  g_h3[LSEQ * ORDER];
__device__ float  g_k [DMODEL * LSEQ];
__device__ float  g_decayA[DMODEL * 64];
__device__ float  g_decayB[DMODEL * 64];
__device__ float2 g_tw[1025];    // eighth-wave table of W8192: w[j]=exp(-2*pi*i*j/8192), j in [0,1024]

// =====================================================================
// Kernel 1: implicit-filter MLP. 2 rows per warp, 8 warps -> 16 rows/CTA.
// grid 256. Also fills decay + twiddle tables.
// =====================================================================
#define MLP_BLOCKS 256
__global__ __launch_bounds__(256) void k_filter_mlp(
    const float* __restrict__ z, const float* __restrict__ deltas,
    const float* __restrict__ W1, const float* __restrict__ b1,
    const float* __restrict__ freq, const float* __restrict__ W2,
    const float* __restrict__ b2, const float* __restrict__ W3,
    const float* __restrict__ b3)
{
    __shared__ float sW1[ORDER * EMB], sb1[ORDER], sb2[ORDER], sb3[ORDER], sfreq[ORDER];
    __shared__ float sW2T[ORDER][ORDER + 1];   // transposed: [j][o]
    __shared__ float sW3T[ORDER][ORDER + 1];
    __shared__ float hb1[8][2][ORDER], hb2[8][2][ORDER];

    int tid = threadIdx.x;
    int wid = tid >> 5, lane = tid & 31;

    for (int i = tid; i < ORDER * EMB; i += 256) sW1[i] = W1[i];
    for (int i = tid; i < ORDER * ORDER; i += 256) {
        int o = i >> 6, j = i & 63;
        sW2T[j][o] = W2[i];
        sW3T[j][o] = W3[i];
    }
    if (tid < ORDER) { sb1[tid] = b1[tid]; sb2[tid] = b2[tid]; sb3[tid] = b3[tid]; sfreq[tid] = freq[tid]; }
    __syncthreads();

    int lbase = blockIdx.x * 16 + wid * 2;
    int o0 = lane, o1 = lane + 32;
    float f0 = sfreq[o0], f1 = sfreq[o1];

    // layer 1
    float a0[2], a1[2];
#pragma unroll
    for (int rr = 0; rr < 2; rr++) { a0[rr] = sb1[o0]; a1[rr] = sb1[o1]; }
#pragma unroll
    for (int e = 0; e < EMB; e++) {
        float w0 = sW1[o0 * EMB + e], w1 = sW1[o1 * EMB + e];
#pragma unroll
        for (int rr = 0; rr < 2; rr++) {
            float zv = z[(lbase + rr) * EMB + e];   // broadcast within warp
            a0[rr] += zv * w0;
            a1[rr] += zv * w1;
        }
    }
#pragma unroll
    for (int rr = 0; rr < 2; rr++) {
        hb1[wid][rr][o0] = __sinf(f0 * a0[rr]);
        hb1[wid][rr][o1] = __sinf(f1 * a1[rr]);
    }
    __syncwarp();

    // layer 2
#pragma unroll
    for (int rr = 0; rr < 2; rr++) { a0[rr] = sb2[o0]; a1[rr] = sb2[o1]; }
#pragma unroll 8
    for (int j = 0; j < ORDER; j++) {
        float w0 = sW2T[j][o0], w1 = sW2T[j][o1];
#pragma unroll
        for (int rr = 0; rr < 2; rr++) {
            float hj = hb1[wid][rr][j];
            a0[rr] += hj * w0;
            a1[rr] += hj * w1;
        }
    }
#pragma unroll
    for (int rr = 0; rr < 2; rr++) {
        hb2[wid][rr][o0] = __sinf(f0 * a0[rr]);
        hb2[wid][rr][o1] = __sinf(f1 * a1[rr]);
    }
    __syncwarp();

    // layer 3
#pragma unroll
    for (int rr = 0; rr < 2; rr++) { a0[rr] = sb3[o0]; a1[rr] = sb3[o1]; }
#pragma unroll 8
    for (int j = 0; j < ORDER; j++) {
        float w0 = sW3T[j][o0], w1 = sW3T[j][o1];
#pragma unroll
        for (int rr = 0; rr < 2; rr++) {
            float hj = hb2[wid][rr][j];
            a0[rr] += hj * w0;
            a1[rr] += hj * w1;
        }
    }
#pragma unroll
    for (int rr = 0; rr < 2; rr++) {
        g_h3[(lbase + rr) * ORDER + o0] = __sinf(f0 * a0[rr]);
        g_h3[(lbase + rr) * ORDER + o1] = __sinf(f1 * a1[rr]);
    }

    // decay factorization: decay(d,l) = A[d][l>>6] * B[d][l&63]
    for (int g = blockIdx.x * 256 + tid; g < DMODEL * 64; g += MLP_BLOCKS * 256) {
        int i = g & 63;
        float a = fabsf(deltas[g >> 6]);
        g_decayA[g] = __expf(-a * (64.0f * (float)i) * (1.0f / 4095.0f));
        g_decayB[g] = __expf(-a * (float)i * (1.0f / 4095.0f));
    }
    // eighth-wave twiddle table
    for (int g = blockIdx.x * 256 + tid; g < 1025; g += MLP_BLOCKS * 256) {
        float ang = -2.0f * 3.14159265358979323846f * (float)g * (1.0f / 8192.0f);
        float s, c;
        sincosf(ang, &s, &c);
        g_tw[g] = make_float2(c, s);
    }
}

// =====================================================================
// Kernel 2: k[d][l] = (h3[l][:] . W4[d][:]) * decay(d,l)
// =====================================================================
__global__ __launch_bounds__(256) void k_filter_gemm(const float* __restrict__ W4)
{
    __shared__ float sh[64][65];
    __shared__ float sw[64][65];
    int lt = blockIdx.x, dt = blockIdx.y;
    int tid = threadIdx.x;

    for (int i = tid; i < 64 * 64; i += 256) {
        int row = i >> 6, col = i & 63;
        sh[row][col] = g_h3[(lt * 64 + row) * 64 + col];
        sw[row][col] = W4[(dt * 64 + row) * 64 + col];
    }
    __syncthreads();

    int tx = tid & 15, ty = tid >> 4;
    float acc[4][4];
#pragma unroll
    for (int r = 0; r < 4; r++)
#pragma unroll
        for (int c = 0; c < 4; c++) acc[r][c] = 0.0f;

#pragma unroll 8
    for (int o = 0; o < 64; o++) {
        float a[4], b[4];
#pragma unroll
        for (int r = 0; r < 4; r++) a[r] = sh[tx + 16 * r][o];
#pragma unroll
        for (int c = 0; c < 4; c++) b[c] = sw[ty + 16 * c][o];
#pragma unroll
        for (int r = 0; r < 4; r++)
#pragma unroll
            for (int c = 0; c < 4; c++) acc[r][c] += a[r] * b[c];
    }

#pragma unroll
    for (int c = 0; c < 4; c++) {
        int d = dt * 64 + ty + 16 * c;
        float dA = g_decayA[d * 64 + lt];
#pragma unroll
        for (int r = 0; r < 4; r++) {
            int li = tx + 16 * r;
            g_k[(size_t)d * LSEQ + lt * 64 + li] = acc[r][c] * dA * g_decayB[d * 64 + li];
        }
    }
}

// =====================================================================
// Kernel 3: per-channel 8192-pt FFT convolution (R4 skeleton + register
// seams). 8192 = 2*16^3: radix-2 fused into loads/product; 3 radix-16
// rounds (ping-pong A/B). Final round ends in registers: product, conj,
// inverse-prep, K spectrum and output all bypass smem.
// =====================================================================
#define PHI(a) ((a) + ((a) >> 4))
#define ABUF 8704
#define TWOFF (2 * 8704)
#define SMEMF2 (2 * 8704 + 1056)
#define SLOT(r) ((((r) & 3) << 2) | ((r) >> 2))

__device__ __forceinline__ float2 cmul(float2 a, float2 b) {
    return make_float2(a.x * b.x - a.y * b.y, a.x * b.y + a.y * b.x);
}
__device__ __forceinline__ float2 cmulc(float2 a, float cr, float ci) {
    return make_float2(a.x * cr - a.y * ci, a.x * ci + a.y * cr);
}
__device__ __forceinline__ float2 cadd(float2 a, float2 b) { return make_float2(a.x + b.x, a.y + b.y); }
__device__ __forceinline__ float2 csub(float2 a, float2 b) { return make_float2(a.x - b.x, a.y - b.y); }
__device__ __forceinline__ float2 cmulnegi(float2 a) { return make_float2(a.y, -a.x); }

// W8192^e for e in [0,8192): eighth table + reflection + quadrant rotation
__device__ __forceinline__ float2 twget8(const float2* __restrict__ tw, int e) {
    int j = e & 2047;
    float2 c;
    if (j <= 1024) {
        c = tw[j];
    } else {
        float2 t = tw[2048 - j];
        c = make_float2(-t.y, -t.x);
    }
    int k = (e >> 11) & 3;
    if (k == 1)      c = make_float2(c.y, -c.x);
    else if (k == 2) c = make_float2(-c.x, -c.y);
    else if (k == 3) c = make_float2(-c.y, c.x);
    return c;
}

__device__ __forceinline__ void bf4(float2& x0, float2& x1, float2& x2, float2& x3) {
    float2 t0 = cadd(x0, x2), t1 = csub(x0, x2);
    float2 t2 = cadd(x1, x3), t3 = csub(x1, x3);
    float2 it3 = cmulnegi(t3);
    x0 = cadd(t0, t2); x2 = csub(t0, t2);
    x1 = cadd(t1, it3); x3 = csub(t1, it3);
}

#define C16 0.9238795325112867f
#define S16 0.3826834323650898f
#define R2H 0.7071067811865476f

__device__ __forceinline__ void bf16core(float2 a[16]) {
    bf4(a[0], a[4], a[8],  a[12]);
    bf4(a[1], a[5], a[9],  a[13]);
    bf4(a[2], a[6], a[10], a[14]);
    bf4(a[3], a[7], a[11], a[15]);
    a[5]  = cmulc(a[5],  C16, -S16);
    a[9]  = cmulc(a[9],  R2H, -R2H);
    a[13] = cmulc(a[13], S16, -C16);
    a[6]  = cmulc(a[6],  R2H, -R2H);
    a[10] = cmulnegi(a[10]);
    a[14] = cmulc(a[14], -R2H, -R2H);
    a[7]  = cmulc(a[7],  S16, -C16);
    a[11] = cmulc(a[11], -R2H, -R2H);
    a[15] = cmulc(a[15], -C16,  S16);
    bf4(a[0],  a[1],  a[2],  a[3]);
    bf4(a[4],  a[5],  a[6],  a[7]);
    bf4(a[8],  a[9],  a[10], a[11]);
    bf4(a[12], a[13], a[14], a[15]);
}

// Radix-16 Stockham round with smem in/out, stride s = 1<<SLOG. 512 threads.
template <int SLOG>
__device__ __forceinline__ void r16ld_st(const float2* __restrict__ src, float2* __restrict__ dst,
                                         const float2* __restrict__ tws, int tid)
{
    float2 a[16];
    int lb = tid + (tid >> 4);
#pragma unroll
    for (int j = 0; j < 16; j++) a[j] = src[lb + 544 * j];
    bf16core(a);
    int sp = (tid >> SLOG) << SLOG;
#pragma unroll
    for (int r = 1; r < 16; r++) a[SLOT(r)] = cmul(a[SLOT(r)], twget8(tws, r * sp));
    int q = tid & ((1 << SLOG) - 1), p = tid >> SLOG;
    int ob = q + (p << (SLOG + 4));
#pragma unroll
    for (int r = 0; r < 16; r++) { int ad = ob + (r << SLOG); dst[ad + (ad >> 4)] = a[SLOT(r)]; }
    __syncthreads();
}

// Final round (s=512, p=0, twiddle-free): smem -> registers.
// Value at global index tid + 512*r ends in a[SLOT(r)].
__device__ __forceinline__ void r16_last(const float2* __restrict__ src, float2 a[16], int tid)
{
    int lb = tid + (tid >> 4);
#pragma unroll
    for (int j = 0; j < 16; j++) a[j] = src[lb + 544 * j];
    __syncthreads();     // all reads done: callers may overwrite src after this
    bf16core(a);
}

__global__ __launch_bounds__(512, 1) void k_conv(const float* __restrict__ x,
                                                 const float* __restrict__ bias,
                                                 float* __restrict__ out)
{
    extern __shared__ float2 sm[];
    float2* A   = sm;
    float2* B   = sm + ABUF;
    float2* tws = sm + TWOFF;     // 1025 used

    int tid = threadIdx.x;
    int d = blockIdx.x;

    for (int i = tid; i < 1025; i += 512) tws[i] = g_tw[i];
    __syncthreads();

    float2 a[16], Kc[16];

    // ---- K spectrum: fused radix-2 (zero-padded) + 3 rounds -> registers ----
    const float* kg = g_k + (size_t)d * LSEQ;
#pragma unroll
    for (int it = 0; it < 8; it++) {
        int p = tid + it * 512;
        float v = kg[p];
        float2 w = twget8(tws, p);
        int o = PHI(2 * p);
        A[o]     = make_float2(v, 0.0f);
        A[o + 1] = make_float2(v * w.x, v * w.y);
    }
    __syncthreads();
    r16ld_st<1>(A, B, tws, tid);
    r16ld_st<5>(B, A, tws, tid);
    r16_last(A, a, tid);
#pragma unroll
    for (int r = 0; r < 16; r++) Kc[r] = a[SLOT(r)];   // K[tid + 512r]

    float bd = bias[d];
    const float inv = 1.0f / 8192.0f;

#pragma unroll
    for (int pr = 0; pr < 2; pr++) {
        const float* x0 = x + ((size_t)(2 * pr) * DMODEL + d) * LSEQ;
        const float* x1 = x + ((size_t)(2 * pr + 1) * DMODEL + d) * LSEQ;

        // forward FFT of packed x0 + i*x1: fused radix-2 from global
        float xr0[8], xr1[8];
#pragma unroll
        for (int it = 0; it < 8; it++) {
            int p = tid + it * 512;
            xr0[it] = x0[p];
            xr1[it] = x1[p];
            float2 v = make_float2(xr0[it], xr1[it]);
            float2 w = twget8(tws, p);
            int o = PHI(2 * p);
            A[o]     = v;
            A[o + 1] = cmul(v, w);
        }
        __syncthreads();
        r16ld_st<1>(A, B, tws, tid);
        r16ld_st<5>(B, A, tws, tid);
        r16_last(A, a, tid);           // W spectrum at tid+512r in regs

        // product with K + conj + inverse's fused radix-2, all in registers
#pragma unroll
        for (int r = 0; r < 8; r++) {
            int p = tid + 512 * r;
            float2 zl = cmul(a[SLOT(r)],     Kc[r]);     zl.y = -zl.y;
            float2 zh = cmul(a[SLOT(r + 8)], Kc[r + 8]); zh.y = -zh.y;
            float2 s = cadd(zl, zh);
            float2 dd = cmul(csub(zl, zh), twget8(tws, p));
            int o = PHI(2 * p);
            A[o]     = s;
            A[o + 1] = dd;
        }
        __syncthreads();
        r16ld_st<1>(A, B, tws, tid);
        r16ld_st<5>(B, A, tws, tid);
        r16_last(A, a, tid);           // fft(conj Z) at tid+512r in regs

        // ifft = conj(.)/N; only indices < 4096 are the valid linear-conv part
        float* o0 = out + ((size_t)(2 * pr) * DMODEL + d) * LSEQ;
        float* o1 = out + ((size_t)(2 * pr + 1) * DMODEL + d) * LSEQ;
#pragma unroll
        for (int r = 0; r < 8; r++) {
            int i = tid + 512 * r;
            float2 y = a[SLOT(r)];
            o0[i] =  y.x * inv + xr0[r] * bd;
            o1[i] = -y.y * inv + xr1[r] * bd;
        }
    }
}

// =====================================================================
extern "C" void kernel_launch(void* const* d_in, const int* in_sizes, int n_in,
                              void* d_out, int out_size)
{
    (void)n_in; (void)out_size;
    const float* x = (const float*)d_in[0];
    int base = (in_sizes[1] == 1) ? 2 : 1;
    const float* z      = (const float*)d_in[base + 0];
    const float* deltas = (const float*)d_in[base + 2];
    const float* W1     = (const float*)d_in[base + 3];
    const float* b1     = (const float*)d_in[base + 4];
    const float* freq   = (const float*)d_in[base + 5];
    const float* W2     = (const float*)d_in[base + 6];
    const float* b2     = (const float*)d_in[base + 7];
    const float* W3     = (const float*)d_in[base + 8];
    const float* b3     = (const float*)d_in[base + 9];
    const float* W4     = (const float*)d_in[base + 10];
    const float* bias   = (const float*)d_in[base + 11];
    float* out = (float*)d_out;

    k_filter_mlp<<<MLP_BLOCKS, 256>>>(z, deltas, W1, b1, freq, W2, b2, W3, b3);

    dim3 g2(64, 16);
    k_filter_gemm<<<g2, 256>>>(W4);

    const int smem_bytes = SMEMF2 * (int)sizeof(float2);   // 147,712 B
    cudaFuncSetAttribute(k_conv, cudaFuncAttributeMaxDynamicSharedMemorySize, smem_bytes);
    k_conv<<<DMODEL, 512, smem_bytes>>>(x, bias, out);
}

// round 8
// speedup vs baseline: 1.7139x; 1.3187x over previous
#include <cuda_runtime.h>
#include <math.h>

#define LSEQ   4096
#define DMODEL 1024
#define ORDER  64
#define EMB    5

// ---- scratch (static device globals: allowed) ----
__device__ float  g_h3[LSEQ * ORDER];
__device__ float  g_k [DMODEL * LSEQ];
__device__ float  g_decayA[DMODEL * 64];
__device__ float  g_decayB[DMODEL * 64];

// =====================================================================
// Kernel 1: implicit-filter MLP. 2 rows per warp, 8 warps -> 16 rows/CTA.
// grid 256. Also fills decay tables.
// =====================================================================
#define MLP_BLOCKS 256
__global__ __launch_bounds__(256) void k_filter_mlp(
    const float* __restrict__ z, const float* __restrict__ deltas,
    const float* __restrict__ W1, const float* __restrict__ b1,
    const float* __restrict__ freq, const float* __restrict__ W2,
    const float* __restrict__ b2, const float* __restrict__ W3,
    const float* __restrict__ b3)
{
    __shared__ float sW1[ORDER * EMB], sb1[ORDER], sb2[ORDER], sb3[ORDER], sfreq[ORDER];
    __shared__ float sW2T[ORDER][ORDER + 1];   // transposed: [j][o]
    __shared__ float sW3T[ORDER][ORDER + 1];
    __shared__ float hb1[8][2][ORDER], hb2[8][2][ORDER];

    int tid = threadIdx.x;
    int wid = tid >> 5, lane = tid & 31;

    for (int i = tid; i < ORDER * EMB; i += 256) sW1[i] = W1[i];
    for (int i = tid; i < ORDER * ORDER; i += 256) {
        int o = i >> 6, j = i & 63;
        sW2T[j][o] = W2[i];
        sW3T[j][o] = W3[i];
    }
    if (tid < ORDER) { sb1[tid] = b1[tid]; sb2[tid] = b2[tid]; sb3[tid] = b3[tid]; sfreq[tid] = freq[tid]; }
    __syncthreads();

    int lbase = blockIdx.x * 16 + wid * 2;
    int o0 = lane, o1 = lane + 32;
    float f0 = sfreq[o0], f1 = sfreq[o1];

    // layer 1
    float a0[2], a1[2];
#pragma unroll
    for (int rr = 0; rr < 2; rr++) { a0[rr] = sb1[o0]; a1[rr] = sb1[o1]; }
#pragma unroll
    for (int e = 0; e < EMB; e++) {
        float w0 = sW1[o0 * EMB + e], w1 = sW1[o1 * EMB + e];
#pragma unroll
        for (int rr = 0; rr < 2; rr++) {
            float zv = z[(lbase + rr) * EMB + e];   // broadcast within warp
            a0[rr] += zv * w0;
            a1[rr] += zv * w1;
        }
    }
#pragma unroll
    for (int rr = 0; rr < 2; rr++) {
        hb1[wid][rr][o0] = __sinf(f0 * a0[rr]);
        hb1[wid][rr][o1] = __sinf(f1 * a1[rr]);
    }
    __syncwarp();

    // layer 2
#pragma unroll
    for (int rr = 0; rr < 2; rr++) { a0[rr] = sb2[o0]; a1[rr] = sb2[o1]; }
#pragma unroll 8
    for (int j = 0; j < ORDER; j++) {
        float w0 = sW2T[j][o0], w1 = sW2T[j][o1];
#pragma unroll
        for (int rr = 0; rr < 2; rr++) {
            float hj = hb1[wid][rr][j];
            a0[rr] += hj * w0;
            a1[rr] += hj * w1;
        }
    }
#pragma unroll
    for (int rr = 0; rr < 2; rr++) {
        hb2[wid][rr][o0] = __sinf(f0 * a0[rr]);
        hb2[wid][rr][o1] = __sinf(f1 * a1[rr]);
    }
    __syncwarp();

    // layer 3
#pragma unroll
    for (int rr = 0; rr < 2; rr++) { a0[rr] = sb3[o0]; a1[rr] = sb3[o1]; }
#pragma unroll 8
    for (int j = 0; j < ORDER; j++) {
        float w0 = sW3T[j][o0], w1 = sW3T[j][o1];
#pragma unroll
        for (int rr = 0; rr < 2; rr++) {
            float hj = hb2[wid][rr][j];
            a0[rr] += hj * w0;
            a1[rr] += hj * w1;
        }
    }
#pragma unroll
    for (int rr = 0; rr < 2; rr++) {
        g_h3[(lbase + rr) * ORDER + o0] = __sinf(f0 * a0[rr]);
        g_h3[(lbase + rr) * ORDER + o1] = __sinf(f1 * a1[rr]);
    }

    // decay factorization: decay(d,l) = A[d][l>>6] * B[d][l&63]
    for (int g = blockIdx.x * 256 + tid; g < DMODEL * 64; g += MLP_BLOCKS * 256) {
        int i = g & 63;
        float a = fabsf(deltas[g >> 6]);
        g_decayA[g] = __expf(-a * (64.0f * (float)i) * (1.0f / 4095.0f));
        g_decayB[g] = __expf(-a * (float)i * (1.0f / 4095.0f));
    }
}

// =====================================================================
// Kernel 2: k[d][l] = (h3[l][:] . W4[d][:]) * decay(d,l)
// =====================================================================
__global__ __launch_bounds__(256) void k_filter_gemm(const float* __restrict__ W4)
{
    __shared__ float sh[64][65];
    __shared__ float sw[64][65];
    int lt = blockIdx.x, dt = blockIdx.y;
    int tid = threadIdx.x;

    for (int i = tid; i < 64 * 64; i += 256) {
        int row = i >> 6, col = i & 63;
        sh[row][col] = g_h3[(lt * 64 + row) * 64 + col];
        sw[row][col] = W4[(dt * 64 + row) * 64 + col];
    }
    __syncthreads();

    int tx = tid & 15, ty = tid >> 4;
    float acc[4][4];
#pragma unroll
    for (int r = 0; r < 4; r++)
#pragma unroll
        for (int c = 0; c < 4; c++) acc[r][c] = 0.0f;

#pragma unroll 8
    for (int o = 0; o < 64; o++) {
        float a[4], b[4];
#pragma unroll
        for (int r = 0; r < 4; r++) a[r] = sh[tx + 16 * r][o];
#pragma unroll
        for (int c = 0; c < 4; c++) b[c] = sw[ty + 16 * c][o];
#pragma unroll
        for (int r = 0; r < 4; r++)
#pragma unroll
            for (int c = 0; c < 4; c++) acc[r][c] += a[r] * b[c];
    }

#pragma unroll
    for (int c = 0; c < 4; c++) {
        int d = dt * 64 + ty + 16 * c;
        float dA = g_decayA[d * 64 + lt];
#pragma unroll
        for (int r = 0; r < 4; r++) {
            int li = tx + 16 * r;
            g_k[(size_t)d * LSEQ + lt * 64 + li] = acc[r][c] * dA * g_decayB[d * 64 + li];
        }
    }
}

// =====================================================================
// Kernel 3: per-channel 8192-pt FFT convolution.
// 8192 = 2*16^3: radix-2 fused into loads/product; 3 radix-16 rounds
// (ping-pong A/B), final round ends in registers. ALL twiddles come from
// per-thread cmul chains seeded by 3 sincosf calls -- no table, no LDS.
// K spectrum parked in smem (written once, read once per pair).
// =====================================================================
#define PHI(a) ((a) + ((a) >> 4))
#define ABUF 8704
#define SMEMF2 (2 * 8704 + 8192)
#define SLOT(r) ((((r) & 3) << 2) | ((r) >> 2))

__device__ __forceinline__ float2 cmul(float2 a, float2 b) {
    return make_float2(a.x * b.x - a.y * b.y, a.x * b.y + a.y * b.x);
}
__device__ __forceinline__ float2 cmulc(float2 a, float cr, float ci) {
    return make_float2(a.x * cr - a.y * ci, a.x * ci + a.y * cr);
}
__device__ __forceinline__ float2 cadd(float2 a, float2 b) { return make_float2(a.x + b.x, a.y + b.y); }
__device__ __forceinline__ float2 csub(float2 a, float2 b) { return make_float2(a.x - b.x, a.y - b.y); }
__device__ __forceinline__ float2 cmulnegi(float2 a) { return make_float2(a.y, -a.x); }

__device__ __forceinline__ void bf4(float2& x0, float2& x1, float2& x2, float2& x3) {
    float2 t0 = cadd(x0, x2), t1 = csub(x0, x2);
    float2 t2 = cadd(x1, x3), t3 = csub(x1, x3);
    float2 it3 = cmulnegi(t3);
    x0 = cadd(t0, t2); x2 = csub(t0, t2);
    x1 = cadd(t1, it3); x3 = csub(t1, it3);
}

#define C16 0.9238795325112867f
#define S16 0.3826834323650898f
#define R2H 0.7071067811865476f

__device__ __forceinline__ void bf16core(float2 a[16]) {
    bf4(a[0], a[4], a[8],  a[12]);
    bf4(a[1], a[5], a[9],  a[13]);
    bf4(a[2], a[6], a[10], a[14]);
    bf4(a[3], a[7], a[11], a[15]);
    a[5]  = cmulc(a[5],  C16, -S16);
    a[9]  = cmulc(a[9],  R2H, -R2H);
    a[13] = cmulc(a[13], S16, -C16);
    a[6]  = cmulc(a[6],  R2H, -R2H);
    a[10] = cmulnegi(a[10]);
    a[14] = cmulc(a[14], -R2H, -R2H);
    a[7]  = cmulc(a[7],  S16, -C16);
    a[11] = cmulc(a[11], -R2H, -R2H);
    a[15] = cmulc(a[15], -C16,  S16);
    bf4(a[0],  a[1],  a[2],  a[3]);
    bf4(a[4],  a[5],  a[6],  a[7]);
    bf4(a[8],  a[9],  a[10], a[11]);
    bf4(a[12], a[13], a[14], a[15]);
}

// Radix-16 Stockham round, stride s = 1<<SLOG, 512 threads.
// Twiddle r for this thread = wb^r (wb = W8192^((tid>>SLOG)<<SLOG)),
// generated by a cmul chain -- no table lookups.
template <int SLOG>
__device__ __forceinline__ void r16ch(const float2* __restrict__ src, float2* __restrict__ dst,
                                      float2 wb, int tid)
{
    float2 a[16];
    int lb = tid + (tid >> 4);
#pragma unroll
    for (int j = 0; j < 16; j++) a[j] = src[lb + 544 * j];
    bf16core(a);
    float2 t = wb;
    a[SLOT(1)] = cmul(a[SLOT(1)], t);
#pragma unroll
    for (int r = 2; r < 16; r++) {
        t = cmul(t, wb);
        a[SLOT(r)] = cmul(a[SLOT(r)], t);
    }
    int q = tid & ((1 << SLOG) - 1), p = tid >> SLOG;
    int ob = q + (p << (SLOG + 4));
#pragma unroll
    for (int r = 0; r < 16; r++) { int ad = ob + (r << SLOG); dst[ad + (ad >> 4)] = a[SLOT(r)]; }
    __syncthreads();
}

// Final round (s=512, p=0, twiddle-free): smem -> registers.
// Value at global index tid + 512*r ends in a[SLOT(r)].
__device__ __forceinline__ void r16_last(const float2* __restrict__ src, float2 a[16], int tid)
{
    int lb = tid + (tid >> 4);
#pragma unroll
    for (int j = 0; j < 16; j++) a[j] = src[lb + 544 * j];
    __syncthreads();     // all reads done: callers may overwrite src after this
    bf16core(a);
}

__global__ __launch_bounds__(512, 1) void k_conv(const float* __restrict__ x,
                                                 const float* __restrict__ bias,
                                                 float* __restrict__ out)
{
    extern __shared__ float2 sm[];
    float2* A  = sm;
    float2* B  = sm + ABUF;
    float2* Kb = sm + 2 * ABUF;   // 8192, unpadded

    int tid = threadIdx.x;
    int d = blockIdx.x;

    // per-thread twiddle bases (W = W8192 = exp(-2*pi*i/8192))
    float ss, cc;
    sincosf(-3.14159265358979323846f * (float)tid * (1.0f / 4096.0f), &ss, &cc);
    const float2 wP = make_float2(cc, ss);                    // W^tid
    sincosf(-3.14159265358979323846f * (float)(tid & ~1) * (1.0f / 4096.0f), &ss, &cc);
    const float2 w1 = make_float2(cc, ss);                    // W^(tid&~1)  (round 1 base)
    sincosf(-3.14159265358979323846f * (float)(tid & ~31) * (1.0f / 4096.0f), &ss, &cc);
    const float2 w2 = make_float2(cc, ss);                    // W^(tid&~31) (round 2 base)
    const float2 S512 = make_float2(C16, -S16);               // W^512

    float2 a[16];

    // ---- K spectrum: fused radix-2 (zero-padded) + 3 rounds -> Kb ----
    const float* kg = g_k + (size_t)d * LSEQ;
    {
        float2 w = wP;
#pragma unroll
        for (int it = 0; it < 8; it++) {
            int p = tid + it * 512;
            float v = kg[p];
            int o = PHI(2 * p);
            A[o]     = make_float2(v, 0.0f);
            A[o + 1] = make_float2(v * w.x, v * w.y);
            w = cmul(w, S512);
        }
    }
    __syncthreads();
    r16ch<1>(A, B, w1, tid);
    r16ch<5>(B, A, w2, tid);
    r16_last(A, a, tid);
#pragma unroll
    for (int r = 0; r < 16; r++) Kb[tid + 512 * r] = a[SLOT(r)];

    float bd = bias[d];
    const float inv = 1.0f / 8192.0f;

#pragma unroll
    for (int pr = 0; pr < 2; pr++) {
        const float* x0 = x + ((size_t)(2 * pr) * DMODEL + d) * LSEQ;
        const float* x1 = x + ((size_t)(2 * pr + 1) * DMODEL + d) * LSEQ;

        // forward FFT of packed x0 + i*x1: fused radix-2 from global
        {
            float2 w = wP;
#pragma unroll
            for (int it = 0; it < 8; it++) {
                int p = tid + it * 512;
                float2 v = make_float2(x0[p], x1[p]);
                int o = PHI(2 * p);
                A[o]     = v;
                A[o + 1] = cmul(v, w);
                w = cmul(w, S512);
            }
        }
        __syncthreads();
        r16ch<1>(A, B, w1, tid);
        r16ch<5>(B, A, w2, tid);
        r16_last(A, a, tid);            // W spectrum at tid+512r in regs

        // product with K + conj + inverse's fused radix-2 (regs + Kb reads)
        {
            float2 w = wP;
#pragma unroll
            for (int r = 0; r < 8; r++) {
                int p = tid + 512 * r;
                float2 zl = cmul(a[SLOT(r)],     Kb[p]);        zl.y = -zl.y;
                float2 zh = cmul(a[SLOT(r + 8)], Kb[p + 4096]); zh.y = -zh.y;
                float2 s  = cadd(zl, zh);
                float2 dd = cmul(csub(zl, zh), w);
                int o = PHI(2 * p);
                A[o]     = s;
                A[o + 1] = dd;
                w = cmul(w, S512);
            }
        }
        __syncthreads();
        r16ch<1>(A, B, w1, tid);
        r16ch<5>(B, A, w2, tid);
        r16_last(A, a, tid);            // fft(conj Z) at tid+512r in regs

        // ifft = conj(.)/N; indices < 4096 are the valid linear-conv part
        float* o0 = out + ((size_t)(2 * pr) * DMODEL + d) * LSEQ;
        float* o1 = out + ((size_t)(2 * pr + 1) * DMODEL + d) * LSEQ;
#pragma unroll
        for (int r = 0; r < 8; r++) {
            int i = tid + 512 * r;
            float2 y = a[SLOT(r)];
            o0[i] =  y.x * inv + x0[i] * bd;
            o1[i] = -y.y * inv + x1[i] * bd;
        }
    }
}

// =====================================================================
extern "C" void kernel_launch(void* const* d_in, const int* in_sizes, int n_in,
                              void* d_out, int out_size)
{
    (void)n_in; (void)out_size;
    const float* x = (const float*)d_in[0];
    int base = (in_sizes[1] == 1) ? 2 : 1;
    const float* z      = (const float*)d_in[base + 0];
    const float* deltas = (const float*)d_in[base + 2];
    const float* W1     = (const float*)d_in[base + 3];
    const float* b1     = (const float*)d_in[base + 4];
    const float* freq   = (const float*)d_in[base + 5];
    const float* W2     = (const float*)d_in[base + 6];
    const float* b2     = (const float*)d_in[base + 7];
    const float* W3     = (const float*)d_in[base + 8];
    const float* b3     = (const float*)d_in[base + 9];
    const float* W4     = (const float*)d_in[base + 10];
    const float* bias   = (const float*)d_in[base + 11];
    float* out = (float*)d_out;

    k_filter_mlp<<<MLP_BLOCKS, 256>>>(z, deltas, W1, b1, freq, W2, b2, W3, b3);

    dim3 g2(64, 16);
    k_filter_gemm<<<g2, 256>>>(W4);

    const int smem_bytes = SMEMF2 * (int)sizeof(float2);   // 204,800 B
    cudaFuncSetAttribute(k_conv, cudaFuncAttributeMaxDynamicSharedMemorySize, smem_bytes);
    k_conv<<<DMODEL, 512, smem_bytes>>>(x, bias, out);
}

// round 9
// speedup vs baseline: 1.7565x; 1.0249x over previous
#include <cuda_runtime.h>
#include <math.h>

#define LSEQ   4096
#define DMODEL 1024
#define ORDER  64
#define EMB    5

// ---- scratch (static device globals: allowed) ----
__device__ float  g_h3[LSEQ * ORDER];
__device__ float  g_k [DMODEL * LSEQ];
__device__ float  g_decayA[DMODEL * 64];
__device__ float  g_decayB[DMODEL * 64];

// =====================================================================
// Kernel 1: implicit-filter MLP. 2 rows per warp, 8 warps -> 16 rows/CTA.
// grid 256. Also fills decay tables.
// =====================================================================
#define MLP_BLOCKS 256
__global__ __launch_bounds__(256) void k_filter_mlp(
    const float* __restrict__ z, const float* __restrict__ deltas,
    const float* __restrict__ W1, const float* __restrict__ b1,
    const float* __restrict__ freq, const float* __restrict__ W2,
    const float* __restrict__ b2, const float* __restrict__ W3,
    const float* __restrict__ b3)
{
    __shared__ float sW1[ORDER * EMB], sb1[ORDER], sb2[ORDER], sb3[ORDER], sfreq[ORDER];
    __shared__ float sW2T[ORDER][ORDER + 1];   // transposed: [j][o]
    __shared__ float sW3T[ORDER][ORDER + 1];
    __shared__ float hb1[8][2][ORDER], hb2[8][2][ORDER];

    int tid = threadIdx.x;
    int wid = tid >> 5, lane = tid & 31;

    for (int i = tid; i < ORDER * EMB; i += 256) sW1[i] = W1[i];
    for (int i = tid; i < ORDER * ORDER; i += 256) {
        int o = i >> 6, j = i & 63;
        sW2T[j][o] = W2[i];
        sW3T[j][o] = W3[i];
    }
    if (tid < ORDER) { sb1[tid] = b1[tid]; sb2[tid] = b2[tid]; sb3[tid] = b3[tid]; sfreq[tid] = freq[tid]; }
    __syncthreads();

    int lbase = blockIdx.x * 16 + wid * 2;
    int o0 = lane, o1 = lane + 32;
    float f0 = sfreq[o0], f1 = sfreq[o1];

    // layer 1
    float a0[2], a1[2];
#pragma unroll
    for (int rr = 0; rr < 2; rr++) { a0[rr] = sb1[o0]; a1[rr] = sb1[o1]; }
#pragma unroll
    for (int e = 0; e < EMB; e++) {
        float w0 = sW1[o0 * EMB + e], w1 = sW1[o1 * EMB + e];
#pragma unroll
        for (int rr = 0; rr < 2; rr++) {
            float zv = z[(lbase + rr) * EMB + e];   // broadcast within warp
            a0[rr] += zv * w0;
            a1[rr] += zv * w1;
        }
    }
#pragma unroll
    for (int rr = 0; rr < 2; rr++) {
        hb1[wid][rr][o0] = __sinf(f0 * a0[rr]);
        hb1[wid][rr][o1] = __sinf(f1 * a1[rr]);
    }
    __syncwarp();

    // layer 2
#pragma unroll
    for (int rr = 0; rr < 2; rr++) { a0[rr] = sb2[o0]; a1[rr] = sb2[o1]; }
#pragma unroll 8
    for (int j = 0; j < ORDER; j++) {
        float w0 = sW2T[j][o0], w1 = sW2T[j][o1];
#pragma unroll
        for (int rr = 0; rr < 2; rr++) {
            float hj = hb1[wid][rr][j];
            a0[rr] += hj * w0;
            a1[rr] += hj * w1;
        }
    }
#pragma unroll
    for (int rr = 0; rr < 2; rr++) {
        hb2[wid][rr][o0] = __sinf(f0 * a0[rr]);
        hb2[wid][rr][o1] = __sinf(f1 * a1[rr]);
    }
    __syncwarp();

    // layer 3
#pragma unroll
    for (int rr = 0; rr < 2; rr++) { a0[rr] = sb3[o0]; a1[rr] = sb3[o1]; }
#pragma unroll 8
    for (int j = 0; j < ORDER; j++) {
        float w0 = sW3T[j][o0], w1 = sW3T[j][o1];
#pragma unroll
        for (int rr = 0; rr < 2; rr++) {
            float hj = hb2[wid][rr][j];
            a0[rr] += hj * w0;
            a1[rr] += hj * w1;
        }
    }
#pragma unroll
    for (int rr = 0; rr < 2; rr++) {
        g_h3[(lbase + rr) * ORDER + o0] = __sinf(f0 * a0[rr]);
        g_h3[(lbase + rr) * ORDER + o1] = __sinf(f1 * a1[rr]);
    }

    // decay factorization: decay(d,l) = A[d][l>>6] * B[d][l&63]
    for (int g = blockIdx.x * 256 + tid; g < DMODEL * 64; g += MLP_BLOCKS * 256) {
        int i = g & 63;
        float a = fabsf(deltas[g >> 6]);
        g_decayA[g] = __expf(-a * (64.0f * (float)i) * (1.0f / 4095.0f));
        g_decayB[g] = __expf(-a * (float)i * (1.0f / 4095.0f));
    }
}

// =====================================================================
// Kernel 2: k[d][l] = (h3[l][:] . W4[d][:]) * decay(d,l)
// =====================================================================
__global__ __launch_bounds__(256) void k_filter_gemm(const float* __restrict__ W4)
{
    __shared__ float sh[64][65];
    __shared__ float sw[64][65];
    int lt = blockIdx.x, dt = blockIdx.y;
    int tid = threadIdx.x;

    for (int i = tid; i < 64 * 64; i += 256) {
        int row = i >> 6, col = i & 63;
        sh[row][col] = g_h3[(lt * 64 + row) * 64 + col];
        sw[row][col] = W4[(dt * 64 + row) * 64 + col];
    }
    __syncthreads();

    int tx = tid & 15, ty = tid >> 4;
    float acc[4][4];
#pragma unroll
    for (int r = 0; r < 4; r++)
#pragma unroll
        for (int c = 0; c < 4; c++) acc[r][c] = 0.0f;

#pragma unroll 8
    for (int o = 0; o < 64; o++) {
        float a[4], b[4];
#pragma unroll
        for (int r = 0; r < 4; r++) a[r] = sh[tx + 16 * r][o];
#pragma unroll
        for (int c = 0; c < 4; c++) b[c] = sw[ty + 16 * c][o];
#pragma unroll
        for (int r = 0; r < 4; r++)
#pragma unroll
            for (int c = 0; c < 4; c++) acc[r][c] += a[r] * b[c];
    }

#pragma unroll
    for (int c = 0; c < 4; c++) {
        int d = dt * 64 + ty + 16 * c;
        float dA = g_decayA[d * 64 + lt];
#pragma unroll
        for (int r = 0; r < 4; r++) {
            int li = tx + 16 * r;
            g_k[(size_t)d * LSEQ + lt * 64 + li] = acc[r][c] * dA * g_decayB[d * 64 + li];
        }
    }
}

// =====================================================================
// Kernel 3: per-channel 8192-pt FFT convolution.
// 8192 = 2*16^3: radix-2 fused into loads/product; 3 radix-16 rounds
// (ping-pong A/B), final round ends in registers. Twiddles via per-thread
// scalar cmul chains. Butterfly core uses PACKED f32x2 arithmetic
// (add/sub/mul/fma.rn.f32x2 -> FADD2/FFMA2): complex add/sub = 1 instr.
// =====================================================================
#define PHI(a) ((a) + ((a) >> 4))
#define ABUF 8704
#define SMEMF2 (2 * 8704 + 8192)
#define SLOT(r) ((((r) & 3) << 2) | ((r) >> 2))

typedef unsigned long long c64;   // packed (float x, float y)

__device__ __forceinline__ c64 pk2(float x, float y) {
    c64 u; asm("mov.b64 %0, {%1, %2};" : "=l"(u) : "f"(x), "f"(y)); return u;
}
__device__ __forceinline__ float2 up2(c64 u) {
    float2 v; asm("mov.b64 {%0, %1}, %2;" : "=f"(v.x), "=f"(v.y) : "l"(u)); return v;
}
__device__ __forceinline__ c64 vadd(c64 a, c64 b) {
    c64 r; asm("add.rn.f32x2 %0, %1, %2;" : "=l"(r) : "l"(a), "l"(b)); return r;
}
__device__ __forceinline__ c64 vsub(c64 a, c64 b) {
    c64 r; asm("sub.rn.f32x2 %0, %1, %2;" : "=l"(r) : "l"(a), "l"(b)); return r;
}
__device__ __forceinline__ c64 vmul(c64 a, c64 b) {
    c64 r; asm("mul.rn.f32x2 %0, %1, %2;" : "=l"(r) : "l"(a), "l"(b)); return r;
}
__device__ __forceinline__ c64 vfma(c64 a, c64 b, c64 c) {
    c64 r; asm("fma.rn.f32x2 %0, %1, %2, %3;" : "=l"(r) : "l"(a), "l"(b), "l"(c)); return r;
}
__device__ __forceinline__ c64 vmuli(c64 a)  { float2 v = up2(a); return pk2(-v.y, v.x); }  // +i*a
__device__ __forceinline__ c64 vmulmi(c64 a) { float2 v = up2(a); return pk2(v.y, -v.x); }  // -i*a

// rotate by (cr + i*ci): r = C*a + S*(i*a), C=(cr,cr), S=(ci,ci) packed splats
__device__ __forceinline__ c64 crot(c64 a, c64 C, c64 S) {
    return vfma(S, vmuli(a), vmul(C, a));
}
// apply scalar twiddle (tx + i*ty) to packed value
__device__ __forceinline__ c64 appc(c64 v, float tx, float ty) {
    float2 a = up2(v);
    return pk2(a.x * tx - a.y * ty, a.x * ty + a.y * tx);
}

__device__ __forceinline__ float2 cmul(float2 a, float2 b) {
    return make_float2(a.x * b.x - a.y * b.y, a.x * b.y + a.y * b.x);
}

#define C16 0.9238795325112867f
#define S16 0.3826834323650898f
#define R2H 0.7071067811865476f

struct PKc {
    c64 C16p, S16n, R2Hp, R2Hn, S16p, C16n;
};

__device__ __forceinline__ void bf4p(c64& x0, c64& x1, c64& x2, c64& x3) {
    c64 t0 = vadd(x0, x2), t1 = vsub(x0, x2);
    c64 t2 = vadd(x1, x3), t3 = vsub(x1, x3);
    c64 u = vmuli(t3);               // i*t3
    x0 = vadd(t0, t2); x2 = vsub(t0, t2);
    x1 = vsub(t1, u);  x3 = vadd(t1, u);
}

__device__ __forceinline__ void bf16p(c64 a[16], const PKc& K) {
    bf4p(a[0], a[4], a[8],  a[12]);
    bf4p(a[1], a[5], a[9],  a[13]);
    bf4p(a[2], a[6], a[10], a[14]);
    bf4p(a[3], a[7], a[11], a[15]);
    a[5]  = crot(a[5],  K.C16p, K.S16n);   // W16^1 = (C16, -S16)
    a[9]  = crot(a[9],  K.R2Hp, K.R2Hn);   // W16^2
    a[13] = crot(a[13], K.S16p, K.C16n);   // W16^3
    a[6]  = crot(a[6],  K.R2Hp, K.R2Hn);   // W16^2
    a[10] = vmulmi(a[10]);                 // W16^4 = -i
    a[14] = crot(a[14], K.R2Hn, K.R2Hn);   // W16^6
    a[7]  = crot(a[7],  K.S16p, K.C16n);   // W16^3
    a[11] = crot(a[11], K.R2Hn, K.R2Hn);   // W16^6
    a[15] = crot(a[15], K.C16n, K.S16p);   // W16^9 = (-C16, S16)
    bf4p(a[0],  a[1],  a[2],  a[3]);
    bf4p(a[4],  a[5],  a[6],  a[7]);
    bf4p(a[8],  a[9],  a[10], a[11]);
    bf4p(a[12], a[13], a[14], a[15]);
}

// Radix-16 Stockham round, stride s = 1<<SLOG, 512 threads.
// Twiddle r = wb^r via scalar cmul chain (wb = W8192^((tid>>SLOG)<<SLOG)).
template <int SLOG>
__device__ __forceinline__ void r16ch(const float2* __restrict__ src, float2* __restrict__ dst,
                                      float2 wb, int tid, const PKc& K)
{
    c64 a[16];
    const c64* s = reinterpret_cast<const c64*>(src);
    c64* dd = reinterpret_cast<c64*>(dst);
    int lb = tid + (tid >> 4);
#pragma unroll
    for (int j = 0; j < 16; j++) a[j] = s[lb + 544 * j];
    bf16p(a, K);
    float tx = wb.x, ty = wb.y;
    a[SLOT(1)] = appc(a[SLOT(1)], tx, ty);
#pragma unroll
    for (int r = 2; r < 16; r++) {
        float nx = tx * wb.x - ty * wb.y;
        float ny = tx * wb.y + ty * wb.x;
        tx = nx; ty = ny;
        a[SLOT(r)] = appc(a[SLOT(r)], tx, ty);
    }
    int q = tid & ((1 << SLOG) - 1), p = tid >> SLOG;
    int ob = q + (p << (SLOG + 4));
#pragma unroll
    for (int r = 0; r < 16; r++) { int ad = ob + (r << SLOG); dd[ad + (ad >> 4)] = a[SLOT(r)]; }
    __syncthreads();
}

// Final round (s=512, p=0, twiddle-free): smem -> registers.
// Value at global index tid + 512*r ends in a[SLOT(r)].
__device__ __forceinline__ void r16_last(const float2* __restrict__ src, c64 a[16], int tid,
                                         const PKc& K)
{
    const c64* s = reinterpret_cast<const c64*>(src);
    int lb = tid + (tid >> 4);
#pragma unroll
    for (int j = 0; j < 16; j++) a[j] = s[lb + 544 * j];
    __syncthreads();     // all reads done: callers may overwrite src after this
    bf16p(a, K);
}

__global__ __launch_bounds__(512, 1) void k_conv(const float* __restrict__ x,
                                                 const float* __restrict__ bias,
                                                 float* __restrict__ out)
{
    extern __shared__ float2 sm[];
    float2* A  = sm;
    float2* B  = sm + ABUF;
    float2* Kb = sm + 2 * ABUF;   // 8192, unpadded

    int tid = threadIdx.x;
    int d = blockIdx.x;

    PKc K;
    K.C16p = pk2(C16, C16);   K.S16n = pk2(-S16, -S16);
    K.R2Hp = pk2(R2H, R2H);   K.R2Hn = pk2(-R2H, -R2H);
    K.S16p = pk2(S16, S16);   K.C16n = pk2(-C16, -C16);

    // per-thread twiddle bases (W = W8192 = exp(-2*pi*i/8192))
    float ss, cc;
    sincosf(-3.14159265358979323846f * (float)tid * (1.0f / 4096.0f), &ss, &cc);
    const float2 wP = make_float2(cc, ss);                    // W^tid
    sincosf(-3.14159265358979323846f * (float)(tid & ~1) * (1.0f / 4096.0f), &ss, &cc);
    const float2 w1 = make_float2(cc, ss);                    // W^(tid&~1)  (round 1 base)
    sincosf(-3.14159265358979323846f * (float)(tid & ~31) * (1.0f / 4096.0f), &ss, &cc);
    const float2 w2 = make_float2(cc, ss);                    // W^(tid&~31) (round 2 base)

    c64 a[16];

    // ---- K spectrum: fused radix-2 (zero-padded) + 3 rounds -> Kb ----
    const float* kg = g_k + (size_t)d * LSEQ;
    {
        float wx = wP.x, wy = wP.y;
#pragma unroll
        for (int it = 0; it < 8; it++) {
            int p = tid + it * 512;
            float v = kg[p];
            int o = PHI(2 * p);
            A[o]     = make_float2(v, 0.0f);
            A[o + 1] = make_float2(v * wx, v * wy);
            float nx = wx * C16 + wy * S16;   // w *= W^512 = (C16, -S16)
            float ny = wy * C16 - wx * S16;
            wx = nx; wy = ny;
        }
    }
    __syncthreads();
    r16ch<1>(A, B, w1, tid, K);
    r16ch<5>(B, A, w2, tid, K);
    r16_last(A, a, tid, K);
#pragma unroll
    for (int r = 0; r < 16; r++) Kb[tid + 512 * r] = up2(a[SLOT(r)]);

    float bd = bias[d];
    const float inv = 1.0f / 8192.0f;

#pragma unroll
    for (int pr = 0; pr < 2; pr++) {
        const float* x0 = x + ((size_t)(2 * pr) * DMODEL + d) * LSEQ;
        const float* x1 = x + ((size_t)(2 * pr + 1) * DMODEL + d) * LSEQ;

        // forward FFT of packed x0 + i*x1: fused radix-2 from global
        {
            float wx = wP.x, wy = wP.y;
#pragma unroll
            for (int it = 0; it < 8; it++) {
                int p = tid + it * 512;
                float2 v = make_float2(x0[p], x1[p]);
                int o = PHI(2 * p);
                A[o]     = v;
                A[o + 1] = cmul(v, make_float2(wx, wy));
                float nx = wx * C16 + wy * S16;
                float ny = wy * C16 - wx * S16;
                wx = nx; wy = ny;
            }
        }
        __syncthreads();
        r16ch<1>(A, B, w1, tid, K);
        r16ch<5>(B, A, w2, tid, K);
        r16_last(A, a, tid, K);         // W spectrum at tid+512r in regs

        // product with K + conj + inverse's fused radix-2 (regs + Kb reads)
        {
            float wx = wP.x, wy = wP.y;
#pragma unroll
            for (int r = 0; r < 8; r++) {
                int p = tid + 512 * r;
                float2 Wl = up2(a[SLOT(r)]);
                float2 Wh = up2(a[SLOT(r + 8)]);
                float2 zl = cmul(Wl, Kb[p]);        zl.y = -zl.y;
                float2 zh = cmul(Wh, Kb[p + 4096]); zh.y = -zh.y;
                float2 s2 = make_float2(zl.x + zh.x, zl.y + zh.y);
                float2 df = make_float2(zl.x - zh.x, zl.y - zh.y);
                int o = PHI(2 * p);
                A[o]     = s2;
                A[o + 1] = cmul(df, make_float2(wx, wy));
                float nx = wx * C16 + wy * S16;
                float ny = wy * C16 - wx * S16;
                wx = nx; wy = ny;
            }
        }
        __syncthreads();
        r16ch<1>(A, B, w1, tid, K);
        r16ch<5>(B, A, w2, tid, K);
        r16_last(A, a, tid, K);         // fft(conj Z) at tid+512r in regs

        // ifft = conj(.)/N; indices < 4096 are the valid linear-conv part
        float* o0 = out + ((size_t)(2 * pr) * DMODEL + d) * LSEQ;
        float* o1 = out + ((size_t)(2 * pr + 1) * DMODEL + d) * LSEQ;
#pragma unroll
        for (int r = 0; r < 8; r++) {
            int i = tid + 512 * r;
            float2 y = up2(a[SLOT(r)]);
            o0[i] =  y.x * inv + x0[i] * bd;
            o1[i] = -y.y * inv + x1[i] * bd;
        }
    }
}

// =====================================================================
extern "C" void kernel_launch(void* const* d_in, const int* in_sizes, int n_in,
                              void* d_out, int out_size)
{
    (void)n_in; (void)out_size;
    const float* x = (const float*)d_in[0];
    int base = (in_sizes[1] == 1) ? 2 : 1;
    const float* z      = (const float*)d_in[base + 0];
    const float* deltas = (const float*)d_in[base + 2];
    const float* W1     = (const float*)d_in[base + 3];
    const float* b1     = (const float*)d_in[base + 4];
    const float* freq   = (const float*)d_in[base + 5];
    const float* W2     = (const float*)d_in[base + 6];
    const float* b2     = (const float*)d_in[base + 7];
    const float* W3     = (const float*)d_in[base + 8];
    const float* b3     = (const float*)d_in[base + 9];
    const float* W4     = (const float*)d_in[base + 10];
    const float* bias   = (const float*)d_in[base + 11];
    float* out = (float*)d_out;

    k_filter_mlp<<<MLP_BLOCKS, 256>>>(z, deltas, W1, b1, freq, W2, b2, W3, b3);

    dim3 g2(64, 16);
    k_filter_gemm<<<g2, 256>>>(W4);

    const int smem_bytes = SMEMF2 * (int)sizeof(float2);   // 204,800 B
    cudaFuncSetAttribute(k_conv, cudaFuncAttributeMaxDynamicSharedMemorySize, smem_bytes);
    k_conv<<<DMODEL, 512, smem_bytes>>>(x, bias, out);
}